// round 8
// baseline (speedup 1.0000x reference)
#include <cuda_runtime.h>
#include <cstdint>

// ============================================================================
// out[b,c] = 8192 - sx[b] - sw[c] + 2*cross[b,c]
//   cross = (weighted x bits u8) @ (w bits s8)^T : M=256, N=4096, K=8192
//   legacy mma.sync int8 (tcgen05 unavailable: harness targets plain sm_100).
// R7 redesign: W quantization fused into the GEMM with NO cross-CTA sync --
// each CTA quantizes its own B tile f32->s8 straight into SMEM (register
// path), relying on L2 to dedupe the 4x duplicated W reads. Hang-free.
// ============================================================================

#define THRESH 0.05f

static constexpr int MDIM = 256;
static constexpr int NDIM = 4096;
static constexpr int FDIM = 4096;
static constexpr int KDIM = 8192;          // bit dim (bytes)

// ---------------- scratch (device globals) -----------------------------------
static __device__ __align__(128) uint8_t g_xa[(size_t)MDIM * KDIM]; // 2 MB
static __device__ float g_sx[MDIM];

// ---------------- PTX helpers ------------------------------------------------
__device__ __forceinline__ uint32_t smem_u32(const void* p) {
    uint32_t a;
    asm("{ .reg .u64 t; cvta.to.shared.u64 t, %1; cvt.u32.u64 %0, t; }"
        : "=r"(a) : "l"(p));
    return a;
}

__device__ __forceinline__ void cp16(uint32_t dst, const void* src) {
    asm volatile("cp.async.cg.shared.global [%0], [%1], 16;"
                 :: "r"(dst), "l"(src) : "memory");
}
#define CP_COMMIT() asm volatile("cp.async.commit_group;" ::: "memory")
#define CP_WAIT2()  asm volatile("cp.async.wait_group 2;" ::: "memory")

__device__ __forceinline__ void mma_u8s8(int32_t* c, const uint32_t* a,
                                         const uint32_t* b) {
    asm volatile(
        "mma.sync.aligned.m16n8k32.row.col.s32.u8.s8.s32 "
        "{%0,%1,%2,%3}, {%4,%5,%6,%7}, {%8,%9}, {%0,%1,%2,%3};"
        : "+r"(c[0]), "+r"(c[1]), "+r"(c[2]), "+r"(c[3])
        : "r"(a[0]), "r"(a[1]), "r"(a[2]), "r"(a[3]), "r"(b[0]), "r"(b[1]));
}

__device__ __forceinline__ void ldsm4(uint32_t& r0, uint32_t& r1, uint32_t& r2,
                                      uint32_t& r3, uint32_t addr) {
    asm volatile("ldmatrix.sync.aligned.m8n8.x4.shared.b16 {%0,%1,%2,%3}, [%4];"
                 : "=r"(r0), "=r"(r1), "=r"(r2), "=r"(r3) : "r"(addr));
}

// ---------------- quant packing ----------------------------------------------
// Feature f (mod 4): neg/pos byte weights (128,64),(32,16),(8,4),(2,1).
template <bool WEIGHTED>
__device__ __forceinline__ uint32_t qpack2(float v0, float v1, float wn0,
                                           float wp0, float wn1, float wp1,
                                           float& s) {
    uint32_t b0 = (v0 <= -THRESH) ? (uint32_t)wn0 : 0u;
    uint32_t b1 = (v0 >=  THRESH) ? (uint32_t)wp0 : 0u;
    uint32_t b2 = (v1 <= -THRESH) ? (uint32_t)wn1 : 0u;
    uint32_t b3 = (v1 >=  THRESH) ? (uint32_t)wp1 : 0u;
    s += (float)(b0 + b1 + b2 + b3);
    if (!WEIGHTED) {
        b0 = b0 ? 1u : 0u; b1 = b1 ? 1u : 0u;
        b2 = b2 ? 1u : 0u; b3 = b3 ? 1u : 0u;
    }
    return b0 | (b1 << 8) | (b2 << 16) | (b3 << 24);
}

// ============================================================================
// quant_x: x f32 -> weighted-bit u8 rows in g_xa + row sums. Small & fast.
// ============================================================================
__global__ void __launch_bounds__(256) quant_x_kernel(const float* __restrict__ x) {
    const int row = blockIdx.x;
    const float4* src = (const float4*)(x + (size_t)row * FDIM);
    uint2* dst = (uint2*)(void*)(g_xa + (size_t)row * KDIM);
    float s = 0.0f;
    float4 v[4];
#pragma unroll
    for (int j = 0; j < 4; j++) v[j] = src[threadIdx.x + j * 256];
#pragma unroll
    for (int j = 0; j < 4; j++) {
        uint2 o;
        o.x = qpack2<true>(v[j].x, v[j].y, 128.f, 64.f, 32.f, 16.f, s);
        o.y = qpack2<true>(v[j].z, v[j].w,   8.f,  4.f,  2.f,  1.f, s);
        dst[threadIdx.x + j * 256] = o;
    }
    __shared__ float red[256];
    red[threadIdx.x] = s;
    __syncthreads();
    for (int off = 128; off > 0; off >>= 1) {
        if (threadIdx.x < off) red[threadIdx.x] += red[threadIdx.x + off];
        __syncthreads();
    }
    if (threadIdx.x == 0) g_sx[row] = red[0];
}

// ============================================================================
// Fused W-quant + GEMM.  BM=64, BN=128, BK=128 bytes (=64 features/chunk).
// A: 4-stage cp.async from g_xa.  B: f32 W -> regs -> quantize -> STS,
// double-buffered in SMEM (chunk it+1 packed during iteration it).
// 256 thr = 8 warps 2(M) x 4(N), warp tile 32x32; SMEM stride 144 B.
// Grid (32, 4) = 128 CTAs, no inter-CTA dependencies.
// ============================================================================

static constexpr int BM = 64;
static constexpr int BN = 128;
static constexpr int BK = 128;                  // bytes per chunk (64 features)
static constexpr int KITERS = KDIM / BK;        // 64
static constexpr int NSTAGES = 4;               // A pipeline depth
static constexpr int STRIDE = 144;
static constexpr int A_STG = BM * STRIDE;       // 9216
static constexpr int A_REG = NSTAGES * A_STG;   // 36864 (A region size)
static constexpr int B_SZ = BN * STRIDE;        // 18432
static constexpr int SMEM_BYTES = A_REG + 2 * B_SZ;  // 73728

__global__ void __launch_bounds__(256, 1)
fused_kernel(const float* __restrict__ w, float* __restrict__ out) {
    extern __shared__ char smem[];
    __shared__ float swacc[BN];

    const uint32_t sb = smem_u32(smem);
    const int tid = threadIdx.x;
    const int wid = tid >> 5;
    const int lane = tid & 31;
    const int wm = wid & 1;          // M warp (32 rows)
    const int wn = wid >> 1;         // N warp (32 cols)
    const int n0 = blockIdx.x * BN;
    const int m0 = blockIdx.y * BM;

    // ---- W quant mapping: 2 threads per B row, 32 features each ------------
    const int qrow = tid >> 1;                    // local B row 0..127
    const int qhalf = tid & 1;                    // feature half of the chunk
    const float* wsrc = w + (size_t)(n0 + qrow) * FDIM + qhalf * 32;
    const uint32_t qsts_base = (uint32_t)(A_REG + qrow * STRIDE + qhalf * 64);

    float4 wreg[8];                               // one chunk's f32 data
    auto ldg_chunk = [&](int c) {
        if (c < KITERS) {
            const float4* p = (const float4*)(wsrc + c * 64);
#pragma unroll
            for (int i = 0; i < 8; i++) wreg[i] = p[i];
        }
    };
    float swsum = 0.0f;
    auto quant_sts = [&](int buf) {
        // wreg[j] covers features (qhalf*32 + 4j .. +3): f mod 4 = 0..3.
#pragma unroll
        for (int j2 = 0; j2 < 4; j2++) {
            uint4 o;
            o.x = qpack2<false>(wreg[2*j2].x,   wreg[2*j2].y,   128.f, 64.f, 32.f, 16.f, swsum);
            o.y = qpack2<false>(wreg[2*j2].z,   wreg[2*j2].w,     8.f,  4.f,  2.f,  1.f, swsum);
            o.z = qpack2<false>(wreg[2*j2+1].x, wreg[2*j2+1].y, 128.f, 64.f, 32.f, 16.f, swsum);
            o.w = qpack2<false>(wreg[2*j2+1].z, wreg[2*j2+1].w,   8.f,  4.f,  2.f,  1.f, swsum);
            *(uint4*)(smem + qsts_base + (uint32_t)buf * B_SZ + 16 * j2) = o;
        }
    };

    // ---- A cp.async: 64 rows x 8 x 16B = 512 chunks -> 2 per thread --------
    const uint8_t* a_src[2]; uint32_t a_dst[2];
#pragma unroll
    for (int i = 0; i < 2; i++) {
        int q = tid + i * 256;
        int r = q >> 3, kc = q & 7;
        a_src[i] = g_xa + (size_t)(m0 + r) * KDIM + kc * 16;
        a_dst[i] = (uint32_t)(r * STRIDE + kc * 16);
    }
    auto load_stage = [&](int s) {
        const uint32_t base = sb + (uint32_t)(s & (NSTAGES - 1)) * A_STG;
        const int ko = s * BK;
#pragma unroll
        for (int i = 0; i < 2; i++) cp16(base + a_dst[i], a_src[i] + ko);
    };

    // ---- ldmatrix per-lane offsets -----------------------------------------
    const int g  = lane >> 3;
    const int lr = lane & 7;
    uint32_t a_lds[2];
#pragma unroll
    for (int mf = 0; mf < 2; mf++)
        a_lds[mf] = (uint32_t)((wm * 32 + mf * 16 + lr + (g & 1) * 8) * STRIDE
                               + (g >> 1) * 16);
    uint32_t b_lds[2];
#pragma unroll
    for (int p = 0; p < 2; p++)
        b_lds[p] = (uint32_t)(A_REG + (wn * 32 + p * 16 + lr + (g >> 1) * 8) * STRIDE
                              + (g & 1) * 16);

    int32_t acc[2][4][4];
#pragma unroll
    for (int mf = 0; mf < 2; mf++)
#pragma unroll
        for (int nf = 0; nf < 4; nf++)
#pragma unroll
            for (int r = 0; r < 4; r++) acc[mf][nf][r] = 0;

    uint32_t afr[2][4];   // [mf][reg]
    uint32_t bfr[4][2];   // [nf][reg]

    // ---- prologue ----------------------------------------------------------
#pragma unroll
    for (int s = 0; s < NSTAGES - 1; ++s) { load_stage(s); CP_COMMIT(); }
    ldg_chunk(0);
    quant_sts(0);          // B chunk 0 -> buf 0
    ldg_chunk(1);          // prefetch chunk 1 f32

    // ---- mainloop ----------------------------------------------------------
    for (int it = 0; it < KITERS; ++it) {
        __syncthreads();                     // math of it-1 done: buf (it+1)&1 free
        if (it + 1 < KITERS) quant_sts((it + 1) & 1);   // pack chunk it+1
        ldg_chunk(it + 2);                   // prefetch f32 for next pack

        CP_WAIT2();                          // A stage it landed (this thread)
        __syncthreads();                     // whole A tile + B STS visible

        const int pf = it + NSTAGES - 1;
        if (pf < KITERS) load_stage(pf);
        CP_COMMIT();

        const uint32_t sbase = sb + (uint32_t)(it & (NSTAGES - 1)) * A_STG;
        const uint32_t bbase = sb + (uint32_t)(it & 1) * B_SZ;
#pragma unroll
        for (int ks = 0; ks < BK / 32; ++ks) {
            const uint32_t kb = (uint32_t)(ks * 32);
#pragma unroll
            for (int mf = 0; mf < 2; mf++)
                ldsm4(afr[mf][0], afr[mf][1], afr[mf][2], afr[mf][3],
                      sbase + a_lds[mf] + kb);
#pragma unroll
            for (int p = 0; p < 2; p++)
                ldsm4(bfr[2*p][0], bfr[2*p][1], bfr[2*p+1][0], bfr[2*p+1][1],
                      bbase + b_lds[p] + kb);
#pragma unroll
            for (int mf = 0; mf < 2; mf++)
#pragma unroll
                for (int nf = 0; nf < 4; nf++)
                    mma_u8s8(acc[mf][nf], afr[mf], bfr[nf]);
        }
    }

    // ---- sw reduction (local; each CTA saw all features of its columns) ----
    swsum += __shfl_xor_sync(0xffffffffu, swsum, 1);
    if ((lane & 1) == 0) swacc[qrow] = swsum;
    __syncthreads();

    // ---- epilogue: out = 8192 - sx[m] - sw[n] + 2*acc  (exact integers) ----
#pragma unroll
    for (int mf = 0; mf < 2; mf++) {
        const int r0 = m0 + wm * 32 + mf * 16 + (lane >> 2);
        const float bx0 = 8192.0f - g_sx[r0];
        const float bx1 = 8192.0f - g_sx[r0 + 8];
#pragma unroll
        for (int nf = 0; nf < 4; nf++) {
            const int cl = wn * 32 + nf * 8 + (lane & 3) * 2;   // local col
            const float sw0 = swacc[cl], sw1 = swacc[cl + 1];
            const int col = n0 + cl;
            float2 v0, v1;
            v0.x = bx0 - sw0 + 2.0f * (float)acc[mf][nf][0];
            v0.y = bx0 - sw1 + 2.0f * (float)acc[mf][nf][1];
            v1.x = bx1 - sw0 + 2.0f * (float)acc[mf][nf][2];
            v1.y = bx1 - sw1 + 2.0f * (float)acc[mf][nf][3];
            *(float2*)(out + (size_t)r0 * NDIM + col) = v0;
            *(float2*)(out + (size_t)(r0 + 8) * NDIM + col) = v1;
        }
    }
}

// ============================================================================
// launcher
// ============================================================================
extern "C" void kernel_launch(void* const* d_in, const int* in_sizes, int n_in,
                              void* d_out, int out_size) {
    (void)in_sizes; (void)n_in; (void)out_size;
    const float* x = (const float*)d_in[0];   // [256, 4096]
    const float* w = (const float*)d_in[1];   // [4096, 4096]
    float* out = (float*)d_out;               // [256, 4096]

    quant_x_kernel<<<MDIM, 256>>>(x);

    cudaFuncSetAttribute(fused_kernel,
                         cudaFuncAttributeMaxDynamicSharedMemorySize, SMEM_BYTES);
    dim3 grid(NDIM / BN, MDIM / BM);          // (32, 4) = 128 CTAs
    fused_kernel<<<grid, 256, SMEM_BYTES>>>(w, out);
}